// round 6
// baseline (speedup 1.0000x reference)
#include <cuda_runtime.h>

#define NB 8
#define NC 16
#define NH 512
#define NW 512
#define NHW (NH * NW)
#define MAXOVF (1 << 20)

// --- dest tiling ---
#define TX 32
#define TY 8
#define NTX (NW / TX)          // 16
#define NTY (NH / TY)          // 64
#define NTILES (NB * NTX * NTY)  // 8192
#define RECCAP 512             // records per tile (mean ~345, 8+ sigma safe)

// --- cell index within a tile: cells (x0,y0) with local clx in [0,32], cly in [0,8]
#define CLW 33
#define CLH 9
#define NCELL (CLW * CLH)      // 297

// --- staged im0 region: src in [X-4, X+35] x [Y-4, Y+11]
#define RX2 40
#define RY2 16
#define PLANE2 (RX2 * RY2)     // 640
#define PSTR2 641              // padded stride

// --- dynamic smem carve (bytes) ---
#define OFF_IM0   0
#define OFF_REC   (OFF_IM0 + NC * PSTR2 * 4)        // 41024
#define OFF_CNT   (OFF_REC + RECCAP * 16)           // 49216
#define OFF_START (OFF_CNT + 304 * 4)               // 50432
#define OFF_CUR   (OFF_START + 304 * 4)             // 51648
#define OFF_ROW   (OFF_CUR + 304 * 4)               // 52864
#define SMEM_BYTES (OFF_ROW + 16 * 4)               // 52928

// Static device scratch (allowed).
__device__ int    g_tcnt[NTILES];
__device__ float4 g_trec[(size_t)NTILES * RECCAP];
__device__ int    g_ovf_cnt;
__device__ float4 g_ovf[MAXOVF];

// ---------------------------------------------------------------------------
// Kernel 1: zero tile counters (tiny now)
// ---------------------------------------------------------------------------
__global__ void k_zero_cnt() {
    int i = blockIdx.x * blockDim.x + threadIdx.x;   // 2048 threads x int4
    ((int4*)g_tcnt)[i] = make_int4(0, 0, 0, 0);
    if (i == 0) g_ovf_cnt = 0;
}

// ---------------------------------------------------------------------------
// Kernel 2: bin sources into per-TILE compact record lists (dup across tile
// boundaries). Large-flow or overflow -> global fallback list w/ corner mask.
// ---------------------------------------------------------------------------
__device__ __forceinline__ void push_ovf(int b, int x0, int y0,
                                         float fx, float fy, int xs, int ys,
                                         unsigned mask) {
    int o = atomicAdd(&g_ovf_cnt, 1);
    if (o < MAXOVF) {
        unsigned packed = (unsigned)(y0 * NW + x0) | ((unsigned)b << 18) |
                          (mask << 21);
        g_ovf[o] = make_float4(__uint_as_float((unsigned)(ys * NW + xs)),
                               fx, fy, __uint_as_float(packed));
    }
}

__device__ __forceinline__ void push_tile(int b, int tpx, int tpy,
                                          int x0, int y0, float fx, float fy,
                                          int xs, int ys) {
    int tile = (b * NTY + tpy) * NTX + tpx;
    int slot = atomicAdd(&g_tcnt[tile], 1);
    int X = tpx * TX, Y = tpy * TY;
    if (slot < RECCAP) {
        unsigned meta = (unsigned)(x0 - X + 1)
                      | ((unsigned)(y0 - Y + 1) << 6)
                      | ((unsigned)(xs - (X - 4)) << 10)
                      | ((unsigned)(ys - (Y - 4)) << 16);
        g_trec[(size_t)tile * RECCAP + slot] =
            make_float4(__uint_as_float(meta), fx, fy, 0.f);
    } else {
        // corners of this record that land in THIS tile's dest range
        unsigned mask = 0;
#pragma unroll
        for (int dy = 0; dy < 2; ++dy)
#pragma unroll
            for (int dx = 0; dx < 2; ++dx) {
                int xd = x0 + dx, yd = y0 + dy;
                if (xd >= X && xd < X + TX && yd >= Y && yd < Y + TY)
                    mask |= 1u << (dy * 2 + dx);
            }
        if (mask) push_ovf(b, x0, y0, fx, fy, xs, ys, mask);
    }
}

__global__ void k_bin(const float* __restrict__ flow) {
    int x = blockIdx.x * blockDim.x + threadIdx.x;
    int y = blockIdx.y;
    int b = blockIdx.z;

    int pix = (b * NH + y) * NW + x;
    float2 f = __ldg((const float2*)flow + pix);

    float xd = (float)x + f.x;
    float yd = (float)y + f.y;
    float x0f = floorf(xd), y0f = floorf(yd);
    int x0 = (int)x0f, y0 = (int)y0f;

    // Reference semantics: scatter only if ALL four corners in-bounds
    if (x0 < 0 || x0 > NW - 2 || y0 < 0 || y0 > NH - 2) return;

    float fx = xd - x0f, fy = yd - y0f;

    if (fabsf(f.x) < 3.0f && fabsf(f.y) < 3.0f) {
        int tpx = x0 >> 5, tpy = y0 >> 3;
        bool dupx = (x0 & (TX - 1)) == TX - 1;   // cell straddles right edge
        bool dupy = (y0 & (TY - 1)) == TY - 1;   // straddles bottom edge
        push_tile(b, tpx, tpy, x0, y0, fx, fy, x, y);
        if (dupx)         push_tile(b, tpx + 1, tpy,     x0, y0, fx, fy, x, y);
        if (dupy)         push_tile(b, tpx,     tpy + 1, x0, y0, fx, fy, x, y);
        if (dupx && dupy) push_tile(b, tpx + 1, tpy + 1, x0, y0, fx, fy, x, y);
    } else {
        push_ovf(b, x0, y0, fx, fy, x, y, 0xFu);   // all 4 corners
    }
}

// ---------------------------------------------------------------------------
// Kernel 3: tiled gather. CTA = 32x8 dest tile. Coalesced-load the tile's
// record list, build per-cell smem index (hist + 2-level scan), stage the
// im0 region in smem, then each thread gathers its dest pixel purely from
// smem and writes BCHW output (+ im1). No atomics on output, no scattered
// global loads.
// ---------------------------------------------------------------------------
__global__ __launch_bounds__(256) void k_gather(const float* __restrict__ im0,
                                                const float* __restrict__ im1,
                                                float* __restrict__ out) {
    extern __shared__ char smem_raw[];
    float*  s_im0   = (float*)(smem_raw + OFF_IM0);
    float4* s_rec   = (float4*)(smem_raw + OFF_REC);
    int*    s_cnt   = (int*)(smem_raw + OFF_CNT);
    int*    s_start = (int*)(smem_raw + OFF_START);
    int*    s_cur   = (int*)(smem_raw + OFF_CUR);
    int*    s_row   = (int*)(smem_raw + OFF_ROW);

    int bx = blockIdx.x, by = blockIdx.y, b = blockIdx.z;
    int X = bx * TX, Y = by * TY;
    int tile = (b * NTY + by) * NTX + bx;
    int tid = threadIdx.y * TX + threadIdx.x;

    int n = min(__ldg(&g_tcnt[tile]), RECCAP);
    const float4* gr = g_trec + (size_t)tile * RECCAP;

    // zero cell counters
    for (int i = tid; i < NCELL; i += 256) s_cnt[i] = 0;

    // stage im0 region [X-4, X+35] x [Y-4, Y+11], 16 channels
    const float* im0b = im0 + (size_t)b * NC * NHW;
    for (int e = tid; e < NC * PLANE2; e += 256) {
        int c   = e / PLANE2;
        int rem = e - c * PLANE2;
        int py  = rem / RX2;
        int px  = rem - py * RX2;
        int gx = X - 4 + px;
        int gy = Y - 4 + py;
        float v = 0.f;
        if (gx >= 0 && gx < NW && gy >= 0 && gy < NH)
            v = __ldg(im0b + (size_t)c * NHW + gy * NW + gx);
        s_im0[c * PSTR2 + rem] = v;
    }
    __syncthreads();

    // pass 1: histogram cells
    for (int i = tid; i < n; i += 256) {
        unsigned meta = __float_as_uint(__ldg(&gr[i].x));
        int cl = ((meta >> 6) & 15) * CLW + (meta & 63);
        atomicAdd(&s_cnt[cl], 1);
    }
    __syncthreads();

    // 2-level exclusive scan: per-row (9 rows of 33), then row offsets
    if (tid < CLH) {
        int base = tid * CLW, run = 0;
        for (int j = 0; j < CLW; ++j) { s_start[base + j] = run; run += s_cnt[base + j]; }
        s_row[tid] = run;
    }
    __syncthreads();
    if (tid == 0) {
        int run = 0;
        for (int j = 0; j < CLH; ++j) { int t = s_row[j]; s_row[j] = run; run += t; }
    }
    __syncthreads();
    for (int i = tid; i < NCELL; i += 256) {
        int v = s_start[i] + s_row[i / CLW];
        s_start[i] = v;
        s_cur[i] = v;
    }
    __syncthreads();

    // pass 2: scatter records into cell-ordered smem list
    for (int i = tid; i < n; i += 256) {
        float4 r = __ldg(&gr[i]);
        unsigned meta = __float_as_uint(r.x);
        int cl = ((meta >> 6) & 15) * CLW + (meta & 63);
        int p = atomicAdd(&s_cur[cl], 1);
        s_rec[p] = r;
    }
    __syncthreads();   // after this, s_cur[cl] == end of cell cl

    // gather: thread = dest pixel
    float acc[NC];
#pragma unroll
    for (int c = 0; c < NC; ++c) acc[c] = 0.f;

#pragma unroll
    for (int dy = 0; dy < 2; ++dy) {
#pragma unroll
        for (int dx = 0; dx < 2; ++dx) {
            int cl = (threadIdx.y + 1 - dy) * CLW + (threadIdx.x + 1 - dx);
            int k0 = s_start[cl], k1 = s_cur[cl];
            for (int k = k0; k < k1; ++k) {
                float4 r = s_rec[k];
                unsigned meta = __float_as_uint(r.x);
                int slx = (meta >> 10) & 63;
                int sly = (meta >> 16) & 15;
                float wx = dx ? r.y : 1.f - r.y;
                float wy = dy ? r.z : 1.f - r.z;
                float w = wx * wy;
                int off = sly * RX2 + slx;
#pragma unroll
                for (int c = 0; c < NC; ++c)
                    acc[c] += w * s_im0[c * PSTR2 + off];
            }
        }
    }

    int x = X + threadIdx.x;
    int y = Y + threadIdx.y;
    size_t o = (size_t)b * NC * NHW + (size_t)y * NW + x;
#pragma unroll
    for (int c = 0; c < NC; ++c)
        out[o + (size_t)c * NHW] = acc[c] + __ldg(im1 + o + (size_t)c * NHW);
}

// ---------------------------------------------------------------------------
// Kernel 4: rare fallback (large flow / tile overflow) -> masked global
// atomic adds on the final BCHW output. Runs after k_gather.
// ---------------------------------------------------------------------------
__global__ void k_ovf(const float* __restrict__ im0, float* __restrict__ out) {
    int total = min(g_ovf_cnt, MAXOVF);
    for (int i = blockIdx.x * blockDim.x + threadIdx.x; i < total;
         i += gridDim.x * blockDim.x) {
        float4 r = g_ovf[i];
        unsigned src_xy = __float_as_uint(r.x);
        unsigned packed = __float_as_uint(r.w);
        int cell = packed & 0x3FFFF;
        int b = (packed >> 18) & 7;
        unsigned mask = (packed >> 21) & 0xF;
        int y0 = cell >> 9, x0 = cell & 511;
        float fx = r.y, fy = r.z;
        const float* sp = im0 + (size_t)b * NC * NHW + src_xy;
        float* ob = out + (size_t)b * NC * NHW;
#pragma unroll
        for (int dy = 0; dy < 2; ++dy) {
#pragma unroll
            for (int dx = 0; dx < 2; ++dx) {
                if (!(mask & (1u << (dy * 2 + dx)))) continue;
                float w = (dx ? fx : 1.f - fx) * (dy ? fy : 1.f - fy);
                float* op = ob + (size_t)(y0 + dy) * NW + (x0 + dx);
#pragma unroll
                for (int c = 0; c < NC; ++c)
                    atomicAdd(op + (size_t)c * NHW, w * __ldg(sp + (size_t)c * NHW));
            }
        }
    }
}

// ---------------------------------------------------------------------------
extern "C" void kernel_launch(void* const* d_in, const int* in_sizes, int n_in,
                              void* d_out, int out_size) {
    const float* im0  = (const float*)d_in[0];
    const float* flow = (const float*)d_in[1];
    const float* im1  = (const float*)d_in[2];
    float* out = (float*)d_out;

    cudaFuncSetAttribute(k_gather, cudaFuncAttributeMaxDynamicSharedMemorySize,
                         SMEM_BYTES);

    k_zero_cnt<<<8, 256>>>();                                    // 8192 ints
    k_bin<<<dim3(NW / 256, NH, NB), 256>>>(flow);
    k_gather<<<dim3(NTX, NTY, NB), dim3(TX, TY), SMEM_BYTES>>>(im0, im1, out);
    k_ovf<<<256, 256>>>(im0, out);
}

// round 7
// speedup vs baseline: 2.9168x; 2.9168x over previous
#include <cuda_runtime.h>
#include <cuda_fp16.h>

#define NB 8
#define NC 16
#define NH 512
#define NW 512
#define NHW (NH * NW)

// Channel-last fp16 accumulator scratch: [B, H, W, C] halves = 67 MB (static, allowed)
__device__ __half g_scr[(size_t)NB * NHW * NC];

// ---------------------------------------------------------------------------
// Kernel 1: zero the scratch (67 MB as uint4 = 4,194,304 elements)
// ---------------------------------------------------------------------------
__global__ void k_zero() {
    size_t i = (size_t)blockIdx.x * blockDim.x + threadIdx.x;
    ((uint4*)g_scr)[i] = make_uint4(0u, 0u, 0u, 0u);
}

// ---------------------------------------------------------------------------
// Kernel 2: forward-warp scatter. fp32 math, fp16 storage via v4.f16x2 REDs.
// 8 RED ops per source (vs 16 with fp32) — halves the LSU-issue bound.
// ---------------------------------------------------------------------------
__device__ __forceinline__ unsigned pk(float a, float b) {
    __half2 h = __floats2half2_rn(a, b);
    return *reinterpret_cast<unsigned*>(&h);
}

__device__ __forceinline__ void red16h(__half* p, unsigned a, unsigned b,
                                       unsigned c, unsigned d) {
    asm volatile("red.global.add.noftz.v4.f16x2 [%0], {%1,%2,%3,%4};"
                 :: "l"(p), "r"(a), "r"(b), "r"(c), "r"(d) : "memory");
}

__device__ __forceinline__ void corner(__half* p, const float* v, float w) {
    red16h(p,
           pk(w * v[0], w * v[1]),  pk(w * v[2], w * v[3]),
           pk(w * v[4], w * v[5]),  pk(w * v[6], w * v[7]));
    red16h(p + 8,
           pk(w * v[8],  w * v[9]),  pk(w * v[10], w * v[11]),
           pk(w * v[12], w * v[13]), pk(w * v[14], w * v[15]));
}

__global__ void k_scatter(const float* __restrict__ im0,
                          const float* __restrict__ flow) {
    int x = blockIdx.x * blockDim.x + threadIdx.x;
    int y = blockIdx.y;
    int b = blockIdx.z;

    int pix = (b * NH + y) * NW + x;
    float2 f = __ldg((const float2*)flow + pix);

    float xd = (float)x + f.x;
    float yd = (float)y + f.y;
    float x0f = floorf(xd), y0f = floorf(yd);
    int x0 = (int)x0f, y0 = (int)y0f;

    // Reference semantics: scatter only if ALL four corners in-bounds
    if (x0 < 0 || x0 > NW - 2 || y0 < 0 || y0 > NH - 2) return;

    float fx = xd - x0f, fy = yd - y0f;
    float wnw = (1.f - fx) * (1.f - fy);
    float wne = fx * (1.f - fy);
    float wsw = (1.f - fx) * fy;
    float wse = fx * fy;

    float v[NC];
    const float* src = im0 + (size_t)b * NC * NHW + (size_t)y * NW + x;
#pragma unroll
    for (int c = 0; c < NC; ++c) v[c] = __ldg(src + (size_t)c * NHW);

    __half* nw = g_scr + ((size_t)(b * NH + y0) * NW + x0) * NC;
    __half* ne = nw + NC;
    __half* sw = nw + (size_t)NW * NC;
    __half* se = sw + NC;

    corner(nw, v, wnw);
    corner(ne, v, wne);
    corner(sw, v, wsw);
    corner(se, v, wse);
}

// ---------------------------------------------------------------------------
// Kernel 3: transpose fp16 [B,H,W,C] scratch -> fp32 [B,C,H,W] output (+ im1)
// ---------------------------------------------------------------------------
__global__ void k_transpose(const float* __restrict__ im1,
                            float* __restrict__ out) {
    __shared__ float s[NC][257];
    int b = blockIdx.y;
    int pbase = blockIdx.x * 256;
    int t = threadIdx.x;

    // 256 pixels x 16 halves = 512 uint4; thread t loads uint4 #t and #(t+256)
    const uint4* src = (const uint4*)(g_scr + ((size_t)b * NHW + pbase) * NC);
#pragma unroll
    for (int i = 0; i < 2; ++i) {
        int j = t + i * 256;
        uint4 u = src[j];
        int pl = j >> 1;            // pixel within tile
        int h0 = (j & 1) * 8;       // first channel in this 16B chunk
        const __half2* hp = (const __half2*)&u;
#pragma unroll
        for (int k = 0; k < 4; ++k) {
            float2 f2 = __half22float2(hp[k]);
            s[h0 + 2 * k][pl]     = f2.x;
            s[h0 + 2 * k + 1][pl] = f2.y;
        }
    }
    __syncthreads();

    size_t o = (size_t)b * NC * NHW + pbase + t;
#pragma unroll
    for (int c = 0; c < NC; ++c) {
        size_t idx = o + (size_t)c * NHW;
        out[idx] = s[c][t] + __ldg(im1 + idx);
    }
}

// ---------------------------------------------------------------------------
extern "C" void kernel_launch(void* const* d_in, const int* in_sizes, int n_in,
                              void* d_out, int out_size) {
    const float* im0  = (const float*)d_in[0];
    const float* flow = (const float*)d_in[1];
    const float* im1  = (const float*)d_in[2];
    float* out = (float*)d_out;

    // scratch halves = 8*512*512*16 -> bytes/16 = 4,194,304 uint4
    k_zero<<<16384, 256>>>();
    k_scatter<<<dim3(NW / 256, NH, NB), 256>>>(im0, flow);
    k_transpose<<<dim3(NHW / 256, NB), 256>>>(im1, out);
}